// round 1
// baseline (speedup 1.0000x reference)
#include <cuda_runtime.h>

#define B_  2
#define L_  2048
#define E_  512
#define H_  8
#define D_  64
#define NF  33      // rfft bins of length-64 signal
#define NC  65      // real coefficients per row: DC + 32*(cos,sin)
#define BH  (B_*H_)

// -------- scratch (static device arrays; no allocations) --------
__device__ float g_basis[NC * L_];                 // [k][t]           520 KB
__device__ float g_C[(size_t)BH * L_ * NC];        // [bh][s][k]       8.5 MB
__device__ float g_invZ[BH * L_];                  // [bh][s]
__device__ float g_P[(size_t)BH * L_ * L_];        // [bh][s][t]       268 MB

// ============ K0: basis table  basis[k][t] ============
__global__ void basis_kernel() {
    int idx = blockIdx.x * blockDim.x + threadIdx.x;
    if (idx >= NC * L_) return;
    int t  = idx % L_;
    int kk = idx / L_;
    float v;
    if (kk == 0) {
        v = 1.0f;
    } else {
        int f = (kk + 1) >> 1;
        int r = (f * t) & (L_ - 1);            // exact mod-2048 phase
        float s, c;
        sincospif((float)r * (1.0f / 1024.0f), &s, &c);
        v = (kk & 1) ? c : s;                  // odd kk -> cos, even -> sin
    }
    g_basis[kk * L_ + t] = v;
}

// ============ K1: per-(b,s) 64-pt DFTs -> coeffs, head-mean subtracted ====
__global__ __launch_bounds__(288) void coeff_kernel(const float* __restrict__ q,
                                                    const float* __restrict__ kin) {
    int bs = blockIdx.x;          // b*L + s
    int b  = bs >> 11;
    int s  = bs & (L_ - 1);

    __shared__ float sq[E_], sk[E_];
    __shared__ float twc[64], tws[64];
    __shared__ float A[H_][NC];

    int tid = threadIdx.x;
    for (int i = tid; i < E_; i += blockDim.x) {
        sq[i] = q[(size_t)bs * E_ + i];
        sk[i] = kin[(size_t)bs * E_ + i];
    }
    if (tid < 64) {
        float ss, cc;
        sincospif((float)tid * (1.0f / 32.0f), &ss, &cc);
        twc[tid] = cc; tws[tid] = ss;
    }
    __syncthreads();

    if (tid < H_ * NF) {
        int h = tid / NF, f = tid % NF;
        const float* qh = sq + h * D_;
        const float* kh = sk + h * D_;
        float Qr = 0.f, Qi = 0.f, Kr = 0.f, Ki = 0.f;
#pragma unroll 8
        for (int j = 0; j < 64; j++) {
            int m = (f * j) & 63;
            float c = twc[m], sn = tws[m];
            float qq = qh[j], kk2 = kh[j];
            Qr = fmaf(qq, c, Qr);  Qi = fmaf(-qq, sn, Qi);   // e^{-i th}
            Kr = fmaf(kk2, c, Kr); Ki = fmaf(-kk2, sn, Ki);
        }
        float Xr = Qr * Kr + Qi * Ki;      // Q * conj(K)
        float Xi = Qi * Kr - Qr * Ki;
        if (f == 0) {
            A[h][0] = Xr * (1.0f / 2048.0f);
        } else {
            A[h][2 * f - 1] =  Xr * (1.0f / 1024.0f);   // pairs with cos
            A[h][2 * f]     = -Xi * (1.0f / 1024.0f);   // pairs with sin
        }
    }
    __syncthreads();

    // subtract head mean (exact: corr linear in coeffs), write [bh][s][k]
    for (int idx = tid; idx < H_ * NC; idx += blockDim.x) {
        int h = idx / NC, kk = idx % NC;
        float m = 0.f;
#pragma unroll
        for (int hh = 0; hh < H_; hh++) m += A[hh][kk];
        m *= (1.0f / H_);
        g_C[((size_t)(b * H_ + h) * L_ + s) * NC + kk] = A[h][kk] - m;
    }
}

// ============ K2: corr GEMM + exp -> P, rowsum -> invZ ============
#define TM 64
#define TN 64
__global__ __launch_bounds__(256) void z_kernel() {
    int bh    = blockIdx.y;
    int sbase = blockIdx.x * TM;

    __shared__ float Cs[NC][68];     // [k][s], padded stride
    __shared__ float Bs[NC][TN];     // [k][t]
    __shared__ float zs[TM][17];

    int tid = threadIdx.x;
    int tx  = tid & 15, ty = tid >> 4;

    // transpose-load coefficient tile (coalesced global read)
    for (int idx = tid; idx < TM * NC; idx += 256) {
        int si = idx / NC, kk = idx % NC;
        Cs[kk][si] = g_C[((size_t)bh * L_ + sbase + si) * NC + kk];
    }

    float zpart[4] = {0.f, 0.f, 0.f, 0.f};
    const size_t Pbase = (size_t)bh * L_ * L_;

    for (int tch = 0; tch < L_ / TN; tch++) {
        int tbase = tch * TN;
        __syncthreads();                       // protect Bs reuse (and Cs on 1st pass)
        for (int idx = tid; idx < NC * TN; idx += 256) {
            int kk = idx / TN, tj = idx % TN;
            Bs[kk][tj] = g_basis[kk * L_ + tbase + tj];
        }
        __syncthreads();

        float acc[4][4] = {};
#pragma unroll 5
        for (int kk = 0; kk < NC; kk++) {
            float4 a  = *(const float4*)&Cs[kk][ty << 2];
            float4 bq = *(const float4*)&Bs[kk][tx << 2];
            acc[0][0] = fmaf(a.x, bq.x, acc[0][0]); acc[0][1] = fmaf(a.x, bq.y, acc[0][1]);
            acc[0][2] = fmaf(a.x, bq.z, acc[0][2]); acc[0][3] = fmaf(a.x, bq.w, acc[0][3]);
            acc[1][0] = fmaf(a.y, bq.x, acc[1][0]); acc[1][1] = fmaf(a.y, bq.y, acc[1][1]);
            acc[1][2] = fmaf(a.y, bq.z, acc[1][2]); acc[1][3] = fmaf(a.y, bq.w, acc[1][3]);
            acc[2][0] = fmaf(a.z, bq.x, acc[2][0]); acc[2][1] = fmaf(a.z, bq.y, acc[2][1]);
            acc[2][2] = fmaf(a.z, bq.z, acc[2][2]); acc[2][3] = fmaf(a.z, bq.w, acc[2][3]);
            acc[3][0] = fmaf(a.w, bq.x, acc[3][0]); acc[3][1] = fmaf(a.w, bq.y, acc[3][1]);
            acc[3][2] = fmaf(a.w, bq.z, acc[3][2]); acc[3][3] = fmaf(a.w, bq.w, acc[3][3]);
        }
#pragma unroll
        for (int i = 0; i < 4; i++) {
            float4 w;
            w.x = __expf(acc[i][0]); w.y = __expf(acc[i][1]);
            w.z = __expf(acc[i][2]); w.w = __expf(acc[i][3]);
            zpart[i] += (w.x + w.y) + (w.z + w.w);
            *(float4*)&g_P[Pbase + (size_t)(sbase + (ty << 2) + i) * L_ + tbase + (tx << 2)] = w;
        }
    }

    __syncthreads();
#pragma unroll
    for (int i = 0; i < 4; i++) zs[(ty << 2) + i][tx] = zpart[i];
    __syncthreads();
    if (tid < TM) {
        float z = 0.f;
#pragma unroll
        for (int j = 0; j < 16; j++) z += zs[tid][j];
        g_invZ[bh * L_ + sbase + tid] = 1.0f / z;
    }
}

// ============ K3: out[l,dd] = sum_s (P[s,l]*invZ[s]) * v[s,dd], scatter ====
#define TL3 128
#define SC3 32
__global__ __launch_bounds__(256) void out_kernel(const float* __restrict__ values,
                                                  float* __restrict__ out) {
    int bh = blockIdx.y;
    int b  = bh >> 3, h = bh & 7;
    int lbase = blockIdx.x * TL3;

    __shared__ float Ws[SC3][TL3];
    __shared__ float Vs[SC3][D_];

    int tid = threadIdx.x;
    int tx  = tid & 15, ty = tid >> 4;

    float acc[8][4] = {};
    const size_t Pbase = (size_t)bh * L_ * L_;

    for (int sch = 0; sch < L_ / SC3; sch++) {
        int sbase = sch * SC3;
        __syncthreads();
        for (int idx = tid; idx < SC3 * (TL3 / 4); idx += 256) {
            int sc = idx / (TL3 / 4), l4 = idx % (TL3 / 4);
            float4 p = *(const float4*)&g_P[Pbase + (size_t)(sbase + sc) * L_ + lbase + l4 * 4];
            float iz = g_invZ[bh * L_ + sbase + sc];
            p.x *= iz; p.y *= iz; p.z *= iz; p.w *= iz;
            *(float4*)&Ws[sc][l4 * 4] = p;
        }
        for (int idx = tid; idx < SC3 * (D_ / 4); idx += 256) {
            int sc = idx / (D_ / 4), d4 = idx % (D_ / 4);
            *(float4*)&Vs[sc][d4 * 4] =
                *(const float4*)&values[((size_t)(b * L_ + sbase + sc)) * E_ + h * D_ + d4 * 4];
        }
        __syncthreads();

#pragma unroll 8
        for (int sc = 0; sc < SC3; sc++) {
            float4 a0 = *(const float4*)&Ws[sc][ty << 3];
            float4 a1 = *(const float4*)&Ws[sc][(ty << 3) + 4];
            float4 bb = *(const float4*)&Vs[sc][tx << 2];
            acc[0][0] = fmaf(a0.x, bb.x, acc[0][0]); acc[0][1] = fmaf(a0.x, bb.y, acc[0][1]);
            acc[0][2] = fmaf(a0.x, bb.z, acc[0][2]); acc[0][3] = fmaf(a0.x, bb.w, acc[0][3]);
            acc[1][0] = fmaf(a0.y, bb.x, acc[1][0]); acc[1][1] = fmaf(a0.y, bb.y, acc[1][1]);
            acc[1][2] = fmaf(a0.y, bb.z, acc[1][2]); acc[1][3] = fmaf(a0.y, bb.w, acc[1][3]);
            acc[2][0] = fmaf(a0.z, bb.x, acc[2][0]); acc[2][1] = fmaf(a0.z, bb.y, acc[2][1]);
            acc[2][2] = fmaf(a0.z, bb.z, acc[2][2]); acc[2][3] = fmaf(a0.z, bb.w, acc[2][3]);
            acc[3][0] = fmaf(a0.w, bb.x, acc[3][0]); acc[3][1] = fmaf(a0.w, bb.y, acc[3][1]);
            acc[3][2] = fmaf(a0.w, bb.z, acc[3][2]); acc[3][3] = fmaf(a0.w, bb.w, acc[3][3]);
            acc[4][0] = fmaf(a1.x, bb.x, acc[4][0]); acc[4][1] = fmaf(a1.x, bb.y, acc[4][1]);
            acc[4][2] = fmaf(a1.x, bb.z, acc[4][2]); acc[4][3] = fmaf(a1.x, bb.w, acc[4][3]);
            acc[5][0] = fmaf(a1.y, bb.x, acc[5][0]); acc[5][1] = fmaf(a1.y, bb.y, acc[5][1]);
            acc[5][2] = fmaf(a1.y, bb.z, acc[5][2]); acc[5][3] = fmaf(a1.y, bb.w, acc[5][3]);
            acc[6][0] = fmaf(a1.z, bb.x, acc[6][0]); acc[6][1] = fmaf(a1.z, bb.y, acc[6][1]);
            acc[6][2] = fmaf(a1.z, bb.z, acc[6][2]); acc[6][3] = fmaf(a1.z, bb.w, acc[6][3]);
            acc[7][0] = fmaf(a1.w, bb.x, acc[7][0]); acc[7][1] = fmaf(a1.w, bb.y, acc[7][1]);
            acc[7][2] = fmaf(a1.w, bb.z, acc[7][2]); acc[7][3] = fmaf(a1.w, bb.w, acc[7][3]);
        }
    }

    // faithful reshape of reference: Vt[b,h,dd,l] -> out[b][dd*32+h*4+(l>>9)][l&511]
    int l1     = lbase >> 9;             // constant within tile (128 | 512)
    int l0base = lbase & 511;
#pragma unroll
    for (int j = 0; j < 4; j++) {
        int dd  = (tx << 2) + j;
        int row = dd * 32 + h * 4 + l1;
        float* op = out + ((size_t)b * 2048 + row) * 512 + l0base + (ty << 3);
        float4 w0, w1;
        w0.x = acc[0][j]; w0.y = acc[1][j]; w0.z = acc[2][j]; w0.w = acc[3][j];
        w1.x = acc[4][j]; w1.y = acc[5][j]; w1.z = acc[6][j]; w1.w = acc[7][j];
        *(float4*)&op[0] = w0;
        *(float4*)&op[4] = w1;
    }
}

// ============ launch ============
extern "C" void kernel_launch(void* const* d_in, const int* in_sizes, int n_in,
                              void* d_out, int out_size) {
    (void)in_sizes; (void)n_in; (void)out_size;
    const float* q = (const float*)d_in[0];
    const float* k = (const float*)d_in[1];
    const float* v = (const float*)d_in[2];
    float* out = (float*)d_out;

    basis_kernel<<<(NC * L_ + 255) / 256, 256>>>();
    coeff_kernel<<<B_ * L_, 288>>>(q, k);
    z_kernel<<<dim3(L_ / TM, BH), 256>>>();
    out_kernel<<<dim3(L_ / TL3, BH), 256>>>(v, out);
}